// round 9
// baseline (speedup 1.0000x reference)
#include <cuda_runtime.h>
#include <cuda_bf16.h>
#include <cstdint>

// GroupQueryAttention: B=2, S=2048, HIDDEN=2048, H=32, HK=8, D=64
// R8: pre-split bf16 hi/lo operands in global; GEMMs are pure bf16 cp.async
// pipelines (no conversions in hot loop); QKV fused; attn writes split output.

#define BATCH 2
#define SEQ 2048
#define HIDDEN 2048
#define NH 32
#define NKV 8
#define HD 64
#define KVDIM 512
#define MTOT (BATCH * SEQ)   // 4096

// ---------------- scratch (static device globals; no allocation) -------------
__device__ __nv_bfloat16 g_xhi[MTOT * HIDDEN], g_xlo[MTOT * HIDDEN];
__device__ __nv_bfloat16 g_wqh[HIDDEN * HIDDEN], g_wql[HIDDEN * HIDDEN];
__device__ __nv_bfloat16 g_wkh[KVDIM * HIDDEN], g_wkl[KVDIM * HIDDEN];
__device__ __nv_bfloat16 g_wvh[KVDIM * HIDDEN], g_wvl[KVDIM * HIDDEN];
__device__ __nv_bfloat16 g_woh[HIDDEN * HIDDEN], g_wol[HIDDEN * HIDDEN];
__device__ __nv_bfloat16 g_qhi[MTOT * HIDDEN], g_qlo[MTOT * HIDDEN];
__device__ __nv_bfloat16 g_khi[MTOT * KVDIM], g_klo[MTOT * KVDIM];
__device__ __nv_bfloat16 g_vhi[MTOT * KVDIM], g_vlo[MTOT * KVDIM];
__device__ __nv_bfloat16 g_ahi[MTOT * HIDDEN], g_alo[MTOT * HIDDEN];

// ======================= PTX helpers (arch-generic, sm_80+) ==================
__device__ __forceinline__ uint32_t smem_u32(const void* p) {
    uint32_t a;
    asm("{ .reg .u64 t; cvta.to.shared.u64 t, %1; cvt.u32.u64 %0, t; }"
        : "=r"(a) : "l"(p));
    return a;
}
__device__ __forceinline__ void ldm_x4(uint32_t* r, uint32_t addr) {
    asm volatile("ldmatrix.sync.aligned.m8n8.x4.shared.b16 {%0,%1,%2,%3}, [%4];"
                 : "=r"(r[0]), "=r"(r[1]), "=r"(r[2]), "=r"(r[3]) : "r"(addr));
}
__device__ __forceinline__ void ldm_x4_t(uint32_t* r, uint32_t addr) {
    asm volatile("ldmatrix.sync.aligned.m8n8.x4.trans.shared.b16 {%0,%1,%2,%3}, [%4];"
                 : "=r"(r[0]), "=r"(r[1]), "=r"(r[2]), "=r"(r[3]) : "r"(addr));
}
__device__ __forceinline__ void mma16816(float* d, const uint32_t* a, const uint32_t* b) {
    asm volatile("mma.sync.aligned.m16n8k16.row.col.f32.bf16.bf16.f32 "
                 "{%0,%1,%2,%3}, {%4,%5,%6,%7}, {%8,%9}, {%0,%1,%2,%3};"
                 : "+f"(d[0]), "+f"(d[1]), "+f"(d[2]), "+f"(d[3])
                 : "r"(a[0]), "r"(a[1]), "r"(a[2]), "r"(a[3]), "r"(b[0]), "r"(b[1]));
}
__device__ __forceinline__ float ex2a(float x) {
    float r;
    asm("ex2.approx.f32 %0, %1;" : "=f"(r) : "f"(x));
    return r;
}
__device__ __forceinline__ void pack_split(float x, float y, uint32_t& hi, uint32_t& lo) {
    uint32_t h;
    asm("cvt.rn.bf16x2.f32 %0, %1, %2;" : "=r"(h) : "f"(y), "f"(x));
    float hx = __uint_as_float(h << 16);
    float hy = __uint_as_float(h & 0xFFFF0000u);
    uint32_t l;
    float lx = x - hx, ly = y - hy;
    asm("cvt.rn.bf16x2.f32 %0, %1, %2;" : "=r"(l) : "f"(ly), "f"(lx));
    hi = h; lo = l;
}
#define CP_ASYNC16(dst, src) \
    asm volatile("cp.async.ca.shared.global [%0], [%1], 16;" :: "r"(dst), "l"(src))
#define CP_ASYNC8(dst, src) \
    asm volatile("cp.async.ca.shared.global [%0], [%1], 8;" :: "r"(dst), "l"(src))
#define CP_COMMIT() asm volatile("cp.async.commit_group;" ::: "memory")
#define CP_WAIT1() asm volatile("cp.async.wait_group 1;" ::: "memory")
#define CP_WAIT0() asm volatile("cp.async.wait_group 0;" ::: "memory")

// ---------------- pre-split: fp32 -> bf16 hi/lo ------------------------------
__global__ __launch_bounds__(256)
void presplit(const float4* __restrict__ src, __nv_bfloat162* __restrict__ hi,
              __nv_bfloat162* __restrict__ lo, int n4)
{
    int i = blockIdx.x * 256 + threadIdx.x;
    if (i >= n4) return;
    float4 v = src[i];
    __nv_bfloat162 h0, h1, l0, l1;
    h0.x = __float2bfloat16(v.x); h0.y = __float2bfloat16(v.y);
    h1.x = __float2bfloat16(v.z); h1.y = __float2bfloat16(v.w);
    l0.x = __float2bfloat16(v.x - __bfloat162float(h0.x));
    l0.y = __float2bfloat16(v.y - __bfloat162float(h0.y));
    l1.x = __float2bfloat16(v.z - __bfloat162float(h1.x));
    l1.y = __float2bfloat16(v.w - __bfloat162float(h1.y));
    hi[2 * i] = h0; hi[2 * i + 1] = h1;
    lo[2 * i] = l0; lo[2 * i + 1] = l1;
}

// ============= pure-bf16 split GEMM core: C = A @ W^T + bias =================
#define BM 128
#define BN 128
#define BK 32
#define STR 40
#define OFFA_HI 0
#define OFFA_LO 5120
#define OFFW_HI 10240
#define OFFW_LO 15360
#define STAGE_EL 20480
#define GEMM_SMEM (2 * STAGE_EL * 2)   // 81920 bytes

__device__ __forceinline__ void gemm_core(
    __nv_bfloat16* sm,
    const __nv_bfloat16* __restrict__ Ahi, const __nv_bfloat16* __restrict__ Alo,
    const __nv_bfloat16* __restrict__ Whi, const __nv_bfloat16* __restrict__ Wlo,
    const float* __restrict__ bias, float* __restrict__ C,
    __nv_bfloat16* __restrict__ Chi, __nv_bfloat16* __restrict__ Clo,
    int mode, int N, int K, int row_base, int col_base)
{
    const int tid = threadIdx.x;
    const int lane = tid & 31, wid = tid >> 5;
    const int wm = wid & 3, wn = wid >> 2;
    const uint32_t sbase = smem_u32(sm);

    float acc[2][8][4];
    #pragma unroll
    for (int i = 0; i < 2; ++i)
        #pragma unroll
        for (int j = 0; j < 8; ++j)
            #pragma unroll
            for (int t = 0; t < 4; ++t) acc[i][j][t] = 0.f;

    const uint32_t aoff = (uint32_t)((wm * 32 + (lane & 15)) * STR) * 2 + (lane >> 4) * 16;
    const uint32_t boff = (uint32_t)((wn * 64 + (lane & 7) + ((lane >> 4) << 3)) * STR) * 2
                        + ((lane >> 3) & 1) * 16;
    const int nit = K / BK;

    auto stage = [&](int i) {
        const int s = i & 1;
        const int k0 = i * BK;
        #pragma unroll
        for (int l = 0; l < 16; ++l) {
            int slot = tid + l * 256;
            int sel = slot >> 10, rem = slot & 1023, r = rem >> 3, c = rem & 7;
            const __nv_bfloat16* src =
                (sel == 0 ? Ahi : sel == 1 ? Alo : sel == 2 ? Whi : Wlo)
                + (size_t)r * K + k0 + c * 4;
            uint32_t dst = sbase + (uint32_t)(s * STAGE_EL + sel * 5120 + r * STR + c * 4) * 2;
            CP_ASYNC8(dst, src);
        }
        CP_COMMIT();
    };

    stage(0);
    for (int i = 0; i < nit; ++i) {
        if (i + 1 < nit) { stage(i + 1); CP_WAIT1(); }
        else CP_WAIT0();
        __syncthreads();

        const uint32_t sa = sbase + (uint32_t)((i & 1) * STAGE_EL) * 2;
        #pragma unroll
        for (int ks = 0; ks < 2; ++ks) {
            const uint32_t kb = ks * 32;
            uint32_t ah[2][4], al[2][4], bh[4][4], bl[4][4];
            #pragma unroll
            for (int mf = 0; mf < 2; ++mf) {
                ldm_x4(ah[mf], sa + OFFA_HI * 2 + aoff + mf * (16 * STR * 2) + kb);
                ldm_x4(al[mf], sa + OFFA_LO * 2 + aoff + mf * (16 * STR * 2) + kb);
            }
            #pragma unroll
            for (int nb = 0; nb < 4; ++nb) {
                ldm_x4(bh[nb], sa + OFFW_HI * 2 + boff + nb * (16 * STR * 2) + kb);
                ldm_x4(bl[nb], sa + OFFW_LO * 2 + boff + nb * (16 * STR * 2) + kb);
            }
            #pragma unroll
            for (int mf = 0; mf < 2; ++mf)
                #pragma unroll
                for (int nf = 0; nf < 8; ++nf) {
                    const uint32_t* bhp = &bh[nf >> 1][(nf & 1) * 2];
                    const uint32_t* blp = &bl[nf >> 1][(nf & 1) * 2];
                    mma16816(acc[mf][nf], ah[mf], bhp);
                    mma16816(acc[mf][nf], ah[mf], blp);
                    mma16816(acc[mf][nf], al[mf], bhp);
                }
        }
        __syncthreads();
    }

    const int row0 = row_base + wm * 32 + (lane >> 2);
    const int col0 = col_base + wn * 64 + 2 * (lane & 3);
    #pragma unroll
    for (int mf = 0; mf < 2; ++mf) {
        #pragma unroll
        for (int nf = 0; nf < 8; ++nf) {
            const int r0 = row0 + mf * 16;
            const int c = col0 + nf * 8;
            const float b0 = bias[c], b1 = bias[c + 1];
            float f00 = acc[mf][nf][0] + b0, f01 = acc[mf][nf][1] + b1;
            float f10 = acc[mf][nf][2] + b0, f11 = acc[mf][nf][3] + b1;
            if (mode == 0) {
                *(float2*)(C + (size_t)r0 * N + c) = make_float2(f00, f01);
                *(float2*)(C + (size_t)(r0 + 8) * N + c) = make_float2(f10, f11);
            } else {
                __nv_bfloat162 h, l;
                h.x = __float2bfloat16(f00); h.y = __float2bfloat16(f01);
                l.x = __float2bfloat16(f00 - __bfloat162float(h.x));
                l.y = __float2bfloat16(f01 - __bfloat162float(h.y));
                *(__nv_bfloat162*)(Chi + (size_t)r0 * N + c) = h;
                *(__nv_bfloat162*)(Clo + (size_t)r0 * N + c) = l;
                h.x = __float2bfloat16(f10); h.y = __float2bfloat16(f11);
                l.x = __float2bfloat16(f10 - __bfloat162float(h.x));
                l.y = __float2bfloat16(f11 - __bfloat162float(h.y));
                *(__nv_bfloat162*)(Chi + (size_t)(r0 + 8) * N + c) = h;
                *(__nv_bfloat162*)(Clo + (size_t)(r0 + 8) * N + c) = l;
            }
        }
    }
}

// ---- fused QKV projection: grid.x = 24 (16 Q tiles | 4 K tiles | 4 V tiles) --
__global__ __launch_bounds__(256)
void qkv_gemm(const __nv_bfloat16* __restrict__ xhi, const __nv_bfloat16* __restrict__ xlo,
              const __nv_bfloat16* __restrict__ wqh, const __nv_bfloat16* __restrict__ wql,
              const __nv_bfloat16* __restrict__ wkh, const __nv_bfloat16* __restrict__ wkl,
              const __nv_bfloat16* __restrict__ wvh, const __nv_bfloat16* __restrict__ wvl,
              const float* __restrict__ bq, const float* __restrict__ bk,
              const float* __restrict__ bv,
              __nv_bfloat16* __restrict__ qhi, __nv_bfloat16* __restrict__ qlo,
              __nv_bfloat16* __restrict__ khi, __nv_bfloat16* __restrict__ klo,
              __nv_bfloat16* __restrict__ vhi, __nv_bfloat16* __restrict__ vlo)
{
    extern __shared__ __align__(16) __nv_bfloat16 sm[];
    const int bx = blockIdx.x, by = blockIdx.y;
    const __nv_bfloat16 *Whi, *Wlo;
    const float* bias;
    __nv_bfloat16 *Chi, *Clo;
    int N, cb;
    if (bx < 16)      { Whi = wqh; Wlo = wql; bias = bq; Chi = qhi; Clo = qlo; N = HIDDEN; cb = bx; }
    else if (bx < 20) { Whi = wkh; Wlo = wkl; bias = bk; Chi = khi; Clo = klo; N = KVDIM; cb = bx - 16; }
    else              { Whi = wvh; Wlo = wvl; bias = bv; Chi = vhi; Clo = vlo; N = KVDIM; cb = bx - 20; }
    gemm_core(sm,
              xhi + (size_t)(by * BM) * HIDDEN, xlo + (size_t)(by * BM) * HIDDEN,
              Whi + (size_t)(cb * BN) * HIDDEN, Wlo + (size_t)(cb * BN) * HIDDEN,
              bias, nullptr, Chi, Clo, 1, N, HIDDEN, by * BM, cb * BN);
}

// ---- output projection ----
__global__ __launch_bounds__(256)
void o_gemm(const __nv_bfloat16* __restrict__ ahi, const __nv_bfloat16* __restrict__ alo,
            const __nv_bfloat16* __restrict__ woh, const __nv_bfloat16* __restrict__ wol,
            const float* __restrict__ bo, float* __restrict__ out)
{
    extern __shared__ __align__(16) __nv_bfloat16 sm[];
    const int bx = blockIdx.x, by = blockIdx.y;
    gemm_core(sm,
              ahi + (size_t)(by * BM) * HIDDEN, alo + (size_t)(by * BM) * HIDDEN,
              woh + (size_t)(bx * BN) * HIDDEN, wol + (size_t)(bx * BN) * HIDDEN,
              bo, out, nullptr, nullptr, 0, HIDDEN, HIDDEN, by * BM, bx * BN);
}

// =================== tensor-core flash attention ==============================
#define ASTR 72
#define A_QLO (128 * ASTR)
#define A_KV  (2 * 128 * ASTR)
#define A_BUF (4 * 64 * ASTR)
#define A_SUB (64 * ASTR)
#define A_SMEM ((A_KV + 2 * A_BUF) * 2)   // 110592 bytes
#define SC_L2E 0.18033688011112042f       // (1/sqrt(64)) * log2(e)

__global__ __launch_bounds__(128)
void gqa_attn_tc(const __nv_bfloat16* __restrict__ qhi, const __nv_bfloat16* __restrict__ qlo,
                 const __nv_bfloat16* __restrict__ khi, const __nv_bfloat16* __restrict__ klo,
                 const __nv_bfloat16* __restrict__ vhi, const __nv_bfloat16* __restrict__ vlo,
                 __nv_bfloat16* __restrict__ Ohi, __nv_bfloat16* __restrict__ Olo)
{
    extern __shared__ __align__(16) __nv_bfloat16 smb[];
    const int tid = threadIdx.x;
    const int lane = tid & 31, warp = tid >> 5;
    const int bh = blockIdx.x, qt = blockIdx.y;
    const int b = bh / NH, h = bh % NH;
    const int kvh = h >> 2;

    const uint32_t sb = smem_u32(smb);
    const __nv_bfloat16* qh = qhi + (size_t)(b * SEQ + qt * 128) * HIDDEN + h * HD;
    const __nv_bfloat16* ql = qlo + (size_t)(b * SEQ + qt * 128) * HIDDEN + h * HD;
    const __nv_bfloat16* kh = khi + (size_t)(b * SEQ) * KVDIM + kvh * HD;
    const __nv_bfloat16* kl = klo + (size_t)(b * SEQ) * KVDIM + kvh * HD;
    const __nv_bfloat16* vh = vhi + (size_t)(b * SEQ) * KVDIM + kvh * HD;
    const __nv_bfloat16* vl = vlo + (size_t)(b * SEQ) * KVDIM + kvh * HD;

    #pragma unroll
    for (int l = 0; l < 16; ++l) {
        int idx = tid + l * 128;
        int sel = idx >> 10, rem = idx & 1023, r = rem >> 3, c = rem & 7;
        const __nv_bfloat16* src = (sel ? ql : qh) + (size_t)r * HIDDEN + c * 8;
        *(uint4*)(smb + sel * A_QLO + r * ASTR + c * 8) = *(const uint4*)src;
    }

    auto stage = [&](int t, int s) {
        #pragma unroll
        for (int l = 0; l < 16; ++l) {
            int idx = tid + l * 128;
            int sel = idx >> 9, rem = idx & 511, r = rem >> 3, c = rem & 7;
            const __nv_bfloat16* src =
                (sel == 0 ? kh : sel == 1 ? kl : sel == 2 ? vh : vl)
                + (size_t)(t * 64 + r) * KVDIM + c * 8;
            uint32_t dst = sb + (uint32_t)(A_KV + s * A_BUF + sel * A_SUB + r * ASTR + c * 8) * 2;
            CP_ASYNC16(dst, src);
        }
    };

    float m_[2][2], l_[2][2], o[2][8][4];
    #pragma unroll
    for (int mf = 0; mf < 2; ++mf) {
        m_[mf][0] = m_[mf][1] = -1e30f;
        l_[mf][0] = l_[mf][1] = 0.f;
        #pragma unroll
        for (int nf = 0; nf < 8; ++nf)
            #pragma unroll
            for (int t = 0; t < 4; ++t) o[mf][nf][t] = 0.f;
    }

    stage(0, 0);
    CP_COMMIT();

    for (int t = 0; t < SEQ / 64; ++t) {
        const int s = t & 1;
        if (t + 1 < SEQ / 64) { stage(t + 1, s ^ 1); CP_COMMIT(); CP_WAIT1(); }
        else CP_WAIT0();
        __syncthreads();

        const uint32_t kb = sb + (uint32_t)(A_KV + s * A_BUF) * 2;

        float sacc[2][8][4];
        #pragma unroll
        for (int mf = 0; mf < 2; ++mf)
            #pragma unroll
            for (int nf = 0; nf < 8; ++nf)
                #pragma unroll
                for (int x = 0; x < 4; ++x) sacc[mf][nf][x] = 0.f;

        #pragma unroll
        for (int ks = 0; ks < 4; ++ks) {
            uint32_t ah[2][4], al[2][4];
            #pragma unroll
            for (int mf = 0; mf < 2; ++mf) {
                uint32_t qa = sb + (uint32_t)((warp * 32 + mf * 16 + (lane & 15)) * ASTR) * 2
                            + (lane >> 4) * 16 + ks * 32;
                ldm_x4(ah[mf], qa);
                ldm_x4(al[mf], qa + A_QLO * 2);
            }
            #pragma unroll
            for (int nb = 0; nb < 4; ++nb) {
                uint32_t bh4[4], bl4[4];
                uint32_t ka = kb + (uint32_t)((nb * 16 + (lane & 7) + ((lane >> 4) << 3)) * ASTR) * 2
                            + ((lane >> 3) & 1) * 16 + ks * 32;
                ldm_x4(bh4, ka);
                ldm_x4(bl4, ka + A_SUB * 2);
                #pragma unroll
                for (int mf = 0; mf < 2; ++mf)
                    #pragma unroll
                    for (int hf = 0; hf < 2; ++hf) {
                        float* d = sacc[mf][nb * 2 + hf];
                        mma16816(d, ah[mf], bh4 + hf * 2);
                        mma16816(d, ah[mf], bl4 + hf * 2);
                        mma16816(d, al[mf], bh4 + hf * 2);
                    }
            }
        }

        #pragma unroll
        for (int mf = 0; mf < 2; ++mf) {
            float r0 = -1e30f, r1 = -1e30f;
            #pragma unroll
            for (int nf = 0; nf < 8; ++nf) {
                r0 = fmaxf(r0, fmaxf(sacc[mf][nf][0], sacc[mf][nf][1]));
                r1 = fmaxf(r1, fmaxf(sacc[mf][nf][2], sacc[mf][nf][3]));
            }
            r0 = fmaxf(r0, __shfl_xor_sync(0xFFFFFFFFu, r0, 1));
            r0 = fmaxf(r0, __shfl_xor_sync(0xFFFFFFFFu, r0, 2));
            r1 = fmaxf(r1, __shfl_xor_sync(0xFFFFFFFFu, r1, 1));
            r1 = fmaxf(r1, __shfl_xor_sync(0xFFFFFFFFu, r1, 2));
            const float mn0 = fmaxf(m_[mf][0], r0);
            const float mn1 = fmaxf(m_[mf][1], r1);
            const float c0 = ex2a((m_[mf][0] - mn0) * SC_L2E);
            const float c1 = ex2a((m_[mf][1] - mn1) * SC_L2E);
            m_[mf][0] = mn0; m_[mf][1] = mn1;
            float rs0 = 0.f, rs1 = 0.f;
            #pragma unroll
            for (int nf = 0; nf < 8; ++nf) {
                float* sp = sacc[mf][nf];
                sp[0] = ex2a((sp[0] - mn0) * SC_L2E);
                sp[1] = ex2a((sp[1] - mn0) * SC_L2E);
                sp[2] = ex2a((sp[2] - mn1) * SC_L2E);
                sp[3] = ex2a((sp[3] - mn1) * SC_L2E);
                rs0 += sp[0] + sp[1];
                rs1 += sp[2] + sp[3];
                o[mf][nf][0] *= c0; o[mf][nf][1] *= c0;
                o[mf][nf][2] *= c1; o[mf][nf][3] *= c1;
            }
            rs0 += __shfl_xor_sync(0xFFFFFFFFu, rs0, 1);
            rs0 += __shfl_xor_sync(0xFFFFFFFFu, rs0, 2);
            rs1 += __shfl_xor_sync(0xFFFFFFFFu, rs1, 1);
            rs1 += __shfl_xor_sync(0xFFFFFFFFu, rs1, 2);
            l_[mf][0] = l_[mf][0] * c0 + rs0;
            l_[mf][1] = l_[mf][1] * c1 + rs1;
        }

        #pragma unroll
        for (int ks2 = 0; ks2 < 4; ++ks2) {
            uint32_t pah[2][4], pal[2][4];
            #pragma unroll
            for (int mf = 0; mf < 2; ++mf) {
                float* s0 = sacc[mf][2 * ks2];
                float* s1 = sacc[mf][2 * ks2 + 1];
                pack_split(s0[0], s0[1], pah[mf][0], pal[mf][0]);
                pack_split(s0[2], s0[3], pah[mf][1], pal[mf][1]);
                pack_split(s1[0], s1[1], pah[mf][2], pal[mf][2]);
                pack_split(s1[2], s1[3], pah[mf][3], pal[mf][3]);
            }
            #pragma unroll
            for (int nblk = 0; nblk < 4; ++nblk) {
                uint32_t vh4[4], vl4[4];
                uint32_t va = kb + (uint32_t)(2 * A_SUB) * 2
                            + (uint32_t)((ks2 * 16 + (lane & 7) + ((lane >> 3) & 1) * 8) * ASTR
                                         + nblk * 16 + (lane >> 4) * 8) * 2;
                ldm_x4_t(vh4, va);
                ldm_x4_t(vl4, va + A_SUB * 2);
                #pragma unroll
                for (int mf = 0; mf < 2; ++mf)
                    #pragma unroll
                    for (int hf = 0; hf < 2; ++hf) {
                        float* d = o[mf][nblk * 2 + hf];
                        mma16816(d, pah[mf], vh4 + hf * 2);
                        mma16816(d, pah[mf], vl4 + hf * 2);
                        mma16816(d, pal[mf], vh4 + hf * 2);
                    }
            }
        }
        __syncthreads();
    }

    // ---- epilogue: write pre-split bf16 hi/lo for the O GEMM ----
    #pragma unroll
    for (int mf = 0; mf < 2; ++mf) {
        const float i0 = 1.f / l_[mf][0];
        const float i1 = 1.f / l_[mf][1];
        const int row = b * SEQ + qt * 128 + warp * 32 + mf * 16 + (lane >> 2);
        #pragma unroll
        for (int nf = 0; nf < 8; ++nf) {
            const int col = h * HD + nf * 8 + (lane & 3) * 2;
            float f00 = o[mf][nf][0] * i0, f01 = o[mf][nf][1] * i0;
            float f10 = o[mf][nf][2] * i1, f11 = o[mf][nf][3] * i1;
            __nv_bfloat162 hh, ll;
            hh.x = __float2bfloat16(f00); hh.y = __float2bfloat16(f01);
            ll.x = __float2bfloat16(f00 - __bfloat162float(hh.x));
            ll.y = __float2bfloat16(f01 - __bfloat162float(hh.y));
            *(__nv_bfloat162*)(Ohi + (size_t)row * HIDDEN + col) = hh;
            *(__nv_bfloat162*)(Olo + (size_t)row * HIDDEN + col) = ll;
            hh.x = __float2bfloat16(f10); hh.y = __float2bfloat16(f11);
            ll.x = __float2bfloat16(f10 - __bfloat162float(hh.x));
            ll.y = __float2bfloat16(f11 - __bfloat162float(hh.y));
            *(__nv_bfloat162*)(Ohi + (size_t)(row + 8) * HIDDEN + col) = hh;
            *(__nv_bfloat162*)(Olo + (size_t)(row + 8) * HIDDEN + col) = ll;
        }
    }
}

// ---------------- launch ------------------------------------------------------
extern "C" void kernel_launch(void* const* d_in, const int* in_sizes, int n_in,
                              void* d_out, int out_size)
{
    const float* x  = (const float*)d_in[0];
    const float* wq = (const float*)d_in[1];
    const float* bq = (const float*)d_in[2];
    const float* wk = (const float*)d_in[3];
    const float* bk = (const float*)d_in[4];
    const float* wv = (const float*)d_in[5];
    const float* bv = (const float*)d_in[6];
    const float* wo = (const float*)d_in[7];
    const float* bo = (const float*)d_in[8];
    float* out = (float*)d_out;

    __nv_bfloat16 *xhi, *xlo, *wqh, *wql, *wkh, *wkl, *wvh, *wvl, *woh, *wol;
    __nv_bfloat16 *qhi, *qlo, *khi, *klo, *vhi, *vlo, *ahi, *alo;
    cudaGetSymbolAddress((void**)&xhi, g_xhi);  cudaGetSymbolAddress((void**)&xlo, g_xlo);
    cudaGetSymbolAddress((void**)&wqh, g_wqh);  cudaGetSymbolAddress((void**)&wql, g_wql);
    cudaGetSymbolAddress((void**)&wkh, g_wkh);  cudaGetSymbolAddress((void**)&wkl, g_wkl);
    cudaGetSymbolAddress((void**)&wvh, g_wvh);  cudaGetSymbolAddress((void**)&wvl, g_wvl);
    cudaGetSymbolAddress((void**)&woh, g_woh);  cudaGetSymbolAddress((void**)&wol, g_wol);
    cudaGetSymbolAddress((void**)&qhi, g_qhi);  cudaGetSymbolAddress((void**)&qlo, g_qlo);
    cudaGetSymbolAddress((void**)&khi, g_khi);  cudaGetSymbolAddress((void**)&klo, g_klo);
    cudaGetSymbolAddress((void**)&vhi, g_vhi);  cudaGetSymbolAddress((void**)&vlo, g_vlo);
    cudaGetSymbolAddress((void**)&ahi, g_ahi);  cudaGetSymbolAddress((void**)&alo, g_alo);

    cudaFuncSetAttribute(qkv_gemm, cudaFuncAttributeMaxDynamicSharedMemorySize, GEMM_SMEM);
    cudaFuncSetAttribute(o_gemm, cudaFuncAttributeMaxDynamicSharedMemorySize, GEMM_SMEM);
    cudaFuncSetAttribute(gqa_attn_tc, cudaFuncAttributeMaxDynamicSharedMemorySize, A_SMEM);

    // pre-split inputs and weights to bf16 hi/lo
    presplit<<<(MTOT * HIDDEN / 4 + 255) / 256, 256>>>(
        (const float4*)x, (__nv_bfloat162*)xhi, (__nv_bfloat162*)xlo, MTOT * HIDDEN / 4);
    presplit<<<(HIDDEN * HIDDEN / 4 + 255) / 256, 256>>>(
        (const float4*)wq, (__nv_bfloat162*)wqh, (__nv_bfloat162*)wql, HIDDEN * HIDDEN / 4);
    presplit<<<(KVDIM * HIDDEN / 4 + 255) / 256, 256>>>(
        (const float4*)wk, (__nv_bfloat162*)wkh, (__nv_bfloat162*)wkl, KVDIM * HIDDEN / 4);
    presplit<<<(KVDIM * HIDDEN / 4 + 255) / 256, 256>>>(
        (const float4*)wv, (__nv_bfloat162*)wvh, (__nv_bfloat162*)wvl, KVDIM * HIDDEN / 4);
    presplit<<<(HIDDEN * HIDDEN / 4 + 255) / 256, 256>>>(
        (const float4*)wo, (__nv_bfloat162*)woh, (__nv_bfloat162*)wol, HIDDEN * HIDDEN / 4);

    // fused Q/K/V projection (pure bf16 pipeline)
    qkv_gemm<<<dim3(24, MTOT / BM), 256, GEMM_SMEM>>>(
        xhi, xlo, wqh, wql, wkh, wkl, wvh, wvl, bq, bk, bv,
        qhi, qlo, khi, klo, vhi, vlo);

    // tensor-core flash attention -> pre-split output
    gqa_attn_tc<<<dim3(BATCH * NH, SEQ / 128), 128, A_SMEM>>>(
        qhi, qlo, khi, klo, vhi, vlo, ahi, alo);

    // output projection
    o_gemm<<<dim3(HIDDEN / BN, MTOT / BM), 256, GEMM_SMEM>>>(
        ahi, alo, woh, wol, bo, out);
}

// round 10
// speedup vs baseline: 1.0625x; 1.0625x over previous
#include <cuda_runtime.h>
#include <cuda_bf16.h>
#include <cstdint>

// GroupQueryAttention: B=2, S=2048, HIDDEN=2048, H=32, HK=8, D=64
// R9: GEMMs reverted to R7 (fastest known); attention now 8 warps/CTA
// (16 q rows per warp) for 2x resident warps -> better latency hiding.

#define BATCH 2
#define SEQ 2048
#define HIDDEN 2048
#define NH 32
#define NKV 8
#define HD 64
#define KVDIM 512
#define MTOT (BATCH * SEQ)   // 4096

// ---------------- scratch (static device globals; no allocation) -------------
__device__ __nv_bfloat16 g_qhi[MTOT * HIDDEN], g_qlo[MTOT * HIDDEN];
__device__ __nv_bfloat16 g_khi[MTOT * KVDIM], g_klo[MTOT * KVDIM];
__device__ __nv_bfloat16 g_vhi[MTOT * KVDIM], g_vlo[MTOT * KVDIM];
__device__ float g_attn[MTOT * HIDDEN];

// ======================= PTX helpers (arch-generic, sm_80+) ==================
__device__ __forceinline__ uint32_t smem_u32(const void* p) {
    uint32_t a;
    asm("{ .reg .u64 t; cvta.to.shared.u64 t, %1; cvt.u32.u64 %0, t; }"
        : "=r"(a) : "l"(p));
    return a;
}
__device__ __forceinline__ void ldm_x4(uint32_t* r, uint32_t addr) {
    asm volatile("ldmatrix.sync.aligned.m8n8.x4.shared.b16 {%0,%1,%2,%3}, [%4];"
                 : "=r"(r[0]), "=r"(r[1]), "=r"(r[2]), "=r"(r[3]) : "r"(addr));
}
__device__ __forceinline__ void ldm_x4_t(uint32_t* r, uint32_t addr) {
    asm volatile("ldmatrix.sync.aligned.m8n8.x4.trans.shared.b16 {%0,%1,%2,%3}, [%4];"
                 : "=r"(r[0]), "=r"(r[1]), "=r"(r[2]), "=r"(r[3]) : "r"(addr));
}
__device__ __forceinline__ void mma16816(float* d, const uint32_t* a, const uint32_t* b) {
    asm volatile("mma.sync.aligned.m16n8k16.row.col.f32.bf16.bf16.f32 "
                 "{%0,%1,%2,%3}, {%4,%5,%6,%7}, {%8,%9}, {%0,%1,%2,%3};"
                 : "+f"(d[0]), "+f"(d[1]), "+f"(d[2]), "+f"(d[3])
                 : "r"(a[0]), "r"(a[1]), "r"(a[2]), "r"(a[3]), "r"(b[0]), "r"(b[1]));
}
__device__ __forceinline__ float ex2a(float x) {
    float r;
    asm("ex2.approx.f32 %0, %1;" : "=f"(r) : "f"(x));
    return r;
}
__device__ __forceinline__ void pack_split(float x, float y, uint32_t& hi, uint32_t& lo) {
    uint32_t h;
    asm("cvt.rn.bf16x2.f32 %0, %1, %2;" : "=r"(h) : "f"(y), "f"(x));
    float hx = __uint_as_float(h << 16);
    float hy = __uint_as_float(h & 0xFFFF0000u);
    uint32_t l;
    float lx = x - hx, ly = y - hy;
    asm("cvt.rn.bf16x2.f32 %0, %1, %2;" : "=r"(l) : "f"(ly), "f"(lx));
    hi = h; lo = l;
}
#define CP_ASYNC16(dst, src) \
    asm volatile("cp.async.ca.shared.global [%0], [%1], 16;" :: "r"(dst), "l"(src))
#define CP_COMMIT() asm volatile("cp.async.commit_group;" ::: "memory")
#define CP_WAIT1() asm volatile("cp.async.wait_group 1;" ::: "memory")
#define CP_WAIT0() asm volatile("cp.async.wait_group 0;" ::: "memory")

// ============= split-bf16 tensor-core GEMM (R7, verified fastest) ============
// mode 0: write fp32 C.  mode 1: write pre-split bf16 hi/lo (for Q/K/V).
#define BM 128
#define BN 128
#define BK 32
#define STR 40
#define OFF_AHI 0
#define OFF_ALO (BM * STR)
#define OFF_BHI (2 * BM * STR)
#define OFF_BLO (2 * BM * STR + BN * STR)
#define STAGE_ELEMS (2 * BM * STR + 2 * BN * STR)
#define GEMM_SMEM (2 * STAGE_ELEMS * 2)

__device__ __forceinline__ void split_store4(__nv_bfloat16* hp, __nv_bfloat16* lp, float4 v) {
    __nv_bfloat16 h0 = __float2bfloat16(v.x), h1 = __float2bfloat16(v.y);
    __nv_bfloat16 h2 = __float2bfloat16(v.z), h3 = __float2bfloat16(v.w);
    __nv_bfloat16 l0 = __float2bfloat16(v.x - __bfloat162float(h0));
    __nv_bfloat16 l1 = __float2bfloat16(v.y - __bfloat162float(h1));
    __nv_bfloat16 l2 = __float2bfloat16(v.z - __bfloat162float(h2));
    __nv_bfloat16 l3 = __float2bfloat16(v.w - __bfloat162float(h3));
    __nv_bfloat162 p;
    p.x = h0; p.y = h1; *(__nv_bfloat162*)(hp)     = p;
    p.x = h2; p.y = h3; *(__nv_bfloat162*)(hp + 2) = p;
    p.x = l0; p.y = l1; *(__nv_bfloat162*)(lp)     = p;
    p.x = l2; p.y = l3; *(__nv_bfloat162*)(lp + 2) = p;
}

__global__ __launch_bounds__(256)
void mma_gemm_split(const float* __restrict__ A, const float* __restrict__ W,
                    const float* __restrict__ bias, float* __restrict__ C,
                    __nv_bfloat16* __restrict__ Chi, __nv_bfloat16* __restrict__ Clo,
                    int mode, int M, int N, int K)
{
    extern __shared__ __align__(16) __nv_bfloat16 sm[];
    const int tid = threadIdx.x;
    const int lane = tid & 31, wid = tid >> 5;
    const int wm = wid & 3;
    const int wn = wid >> 2;
    const int bx = blockIdx.x, by = blockIdx.y;

    const float* Ab = A + (size_t)(by * BM) * K;
    const float* Wb = W + (size_t)(bx * BN) * K;

    float acc[2][8][4];
    #pragma unroll
    for (int i = 0; i < 2; ++i)
        #pragma unroll
        for (int j = 0; j < 8; ++j)
            #pragma unroll
            for (int t = 0; t < 4; ++t) acc[i][j][t] = 0.f;

    float4 ra[4], rb[4];
    const uint32_t sbase = smem_u32(sm);
    const uint32_t aoff = (uint32_t)((wm * 32 + (lane & 15)) * STR) * 2 + (lane >> 4) * 16;
    const uint32_t boff = (uint32_t)((wn * 64 + (lane & 7) + ((lane >> 4) << 3)) * STR) * 2
                        + ((lane >> 3) & 1) * 16;
    const int nit = K / BK;

    {
        #pragma unroll
        for (int l = 0; l < 4; ++l) {
            int slot = tid + l * 256;
            int r = slot >> 3, q = slot & 7;
            ra[l] = *(const float4*)(Ab + (size_t)r * K + q * 4);
            rb[l] = *(const float4*)(Wb + (size_t)r * K + q * 4);
        }
        #pragma unroll
        for (int l = 0; l < 4; ++l) {
            int slot = tid + l * 256;
            int r = slot >> 3, q = slot & 7;
            int off = r * STR + q * 4;
            split_store4(sm + OFF_AHI + off, sm + OFF_ALO + off, ra[l]);
            split_store4(sm + OFF_BHI + off, sm + OFF_BLO + off, rb[l]);
        }
        __syncthreads();
    }

    for (int i = 0; i < nit; ++i) {
        if (i + 1 < nit) {
            const int k0 = (i + 1) * BK;
            #pragma unroll
            for (int l = 0; l < 4; ++l) {
                int slot = tid + l * 256;
                int r = slot >> 3, q = slot & 7;
                ra[l] = *(const float4*)(Ab + (size_t)r * K + k0 + q * 4);
                rb[l] = *(const float4*)(Wb + (size_t)r * K + k0 + q * 4);
            }
        }
        {
            const uint32_t sa = sbase + (uint32_t)((i & 1) * STAGE_ELEMS) * 2;
            #pragma unroll
            for (int ks = 0; ks < 2; ++ks) {
                const uint32_t kb = ks * 32;
                uint32_t ah[2][4], al[2][4], bh[4][4], bl[4][4];
                #pragma unroll
                for (int mf = 0; mf < 2; ++mf) {
                    ldm_x4(ah[mf], sa + OFF_AHI * 2 + aoff + mf * (16 * STR * 2) + kb);
                    ldm_x4(al[mf], sa + OFF_ALO * 2 + aoff + mf * (16 * STR * 2) + kb);
                }
                #pragma unroll
                for (int nb = 0; nb < 4; ++nb) {
                    ldm_x4(bh[nb], sa + OFF_BHI * 2 + boff + nb * (16 * STR * 2) + kb);
                    ldm_x4(bl[nb], sa + OFF_BLO * 2 + boff + nb * (16 * STR * 2) + kb);
                }
                #pragma unroll
                for (int mf = 0; mf < 2; ++mf)
                    #pragma unroll
                    for (int nf = 0; nf < 8; ++nf) {
                        const uint32_t* bhp = &bh[nf >> 1][(nf & 1) * 2];
                        const uint32_t* blp = &bl[nf >> 1][(nf & 1) * 2];
                        mma16816(acc[mf][nf], ah[mf], bhp);
                        mma16816(acc[mf][nf], ah[mf], blp);
                        mma16816(acc[mf][nf], al[mf], bhp);
                    }
            }
        }
        if (i + 1 < nit) {
            __nv_bfloat16* base = sm + ((i + 1) & 1) * STAGE_ELEMS;
            #pragma unroll
            for (int l = 0; l < 4; ++l) {
                int slot = tid + l * 256;
                int r = slot >> 3, q = slot & 7;
                int off = r * STR + q * 4;
                split_store4(base + OFF_AHI + off, base + OFF_ALO + off, ra[l]);
                split_store4(base + OFF_BHI + off, base + OFF_BLO + off, rb[l]);
            }
        }
        __syncthreads();
    }

    const int row0 = by * BM + wm * 32 + (lane >> 2);
    const int col0 = bx * BN + wn * 64 + 2 * (lane & 3);
    #pragma unroll
    for (int mf = 0; mf < 2; ++mf) {
        #pragma unroll
        for (int nf = 0; nf < 8; ++nf) {
            const int r0 = row0 + mf * 16;
            const int c = col0 + nf * 8;
            const float b0 = bias[c], b1 = bias[c + 1];
            float f00 = acc[mf][nf][0] + b0, f01 = acc[mf][nf][1] + b1;
            float f10 = acc[mf][nf][2] + b0, f11 = acc[mf][nf][3] + b1;
            if (mode == 0) {
                *(float2*)(C + (size_t)r0 * N + c) = make_float2(f00, f01);
                *(float2*)(C + (size_t)(r0 + 8) * N + c) = make_float2(f10, f11);
            } else {
                __nv_bfloat162 h, l;
                h.x = __float2bfloat16(f00); h.y = __float2bfloat16(f01);
                l.x = __float2bfloat16(f00 - __bfloat162float(h.x));
                l.y = __float2bfloat16(f01 - __bfloat162float(h.y));
                *(__nv_bfloat162*)(Chi + (size_t)r0 * N + c) = h;
                *(__nv_bfloat162*)(Clo + (size_t)r0 * N + c) = l;
                h.x = __float2bfloat16(f10); h.y = __float2bfloat16(f11);
                l.x = __float2bfloat16(f10 - __bfloat162float(h.x));
                l.y = __float2bfloat16(f11 - __bfloat162float(h.y));
                *(__nv_bfloat162*)(Chi + (size_t)(r0 + 8) * N + c) = h;
                *(__nv_bfloat162*)(Clo + (size_t)(r0 + 8) * N + c) = l;
            }
        }
    }
}

// =================== tensor-core flash attention (8 warps) ====================
// Block: 256 threads (8 warps), 128 q rows -> 16 rows per warp.
#define ASTR 72
#define A_QLO (128 * ASTR)
#define A_KV  (2 * 128 * ASTR)
#define A_BUF (4 * 64 * ASTR)
#define A_SUB (64 * ASTR)
#define A_SMEM ((A_KV + 2 * A_BUF) * 2)   // 110592 bytes
#define SC_L2E 0.18033688011112042f       // (1/sqrt(64)) * log2(e)

__global__ __launch_bounds__(256)
void gqa_attn_tc(const __nv_bfloat16* __restrict__ qhi, const __nv_bfloat16* __restrict__ qlo,
                 const __nv_bfloat16* __restrict__ khi, const __nv_bfloat16* __restrict__ klo,
                 const __nv_bfloat16* __restrict__ vhi, const __nv_bfloat16* __restrict__ vlo,
                 float* __restrict__ O)
{
    extern __shared__ __align__(16) __nv_bfloat16 smb[];
    const int tid = threadIdx.x;
    const int lane = tid & 31, warp = tid >> 5;
    const int bh = blockIdx.x, qt = blockIdx.y;
    const int b = bh / NH, h = bh % NH;
    const int kvh = h >> 2;

    const uint32_t sb = smem_u32(smb);
    const __nv_bfloat16* qh = qhi + (size_t)(b * SEQ + qt * 128) * HIDDEN + h * HD;
    const __nv_bfloat16* ql = qlo + (size_t)(b * SEQ + qt * 128) * HIDDEN + h * HD;
    const __nv_bfloat16* kh = khi + (size_t)(b * SEQ) * KVDIM + kvh * HD;
    const __nv_bfloat16* kl = klo + (size_t)(b * SEQ) * KVDIM + kvh * HD;
    const __nv_bfloat16* vh = vhi + (size_t)(b * SEQ) * KVDIM + kvh * HD;
    const __nv_bfloat16* vl = vlo + (size_t)(b * SEQ) * KVDIM + kvh * HD;

    // ---- load Q tile (hi+lo): 2048 16B slots over 256 threads ----
    #pragma unroll
    for (int l = 0; l < 8; ++l) {
        int idx = tid + l * 256;
        int sel = idx >> 10, rem = idx & 1023, r = rem >> 3, c = rem & 7;
        const __nv_bfloat16* src = (sel ? ql : qh) + (size_t)r * HIDDEN + c * 8;
        *(uint4*)(smb + sel * A_QLO + r * ASTR + c * 8) = *(const uint4*)src;
    }

    auto stage = [&](int t, int s) {
        #pragma unroll
        for (int l = 0; l < 8; ++l) {
            int idx = tid + l * 256;
            int sel = idx >> 9, rem = idx & 511, r = rem >> 3, c = rem & 7;
            const __nv_bfloat16* src =
                (sel == 0 ? kh : sel == 1 ? kl : sel == 2 ? vh : vl)
                + (size_t)(t * 64 + r) * KVDIM + c * 8;
            uint32_t dst = sb + (uint32_t)(A_KV + s * A_BUF + sel * A_SUB + r * ASTR + c * 8) * 2;
            CP_ASYNC16(dst, src);
        }
    };

    float m0 = -1e30f, m1 = -1e30f, l0 = 0.f, l1 = 0.f;
    float o[8][4];
    #pragma unroll
    for (int nf = 0; nf < 8; ++nf)
        #pragma unroll
        for (int t = 0; t < 4; ++t) o[nf][t] = 0.f;

    stage(0, 0);
    CP_COMMIT();

    for (int t = 0; t < SEQ / 64; ++t) {
        const int s = t & 1;
        if (t + 1 < SEQ / 64) { stage(t + 1, s ^ 1); CP_COMMIT(); CP_WAIT1(); }
        else CP_WAIT0();
        __syncthreads();

        const uint32_t kb = sb + (uint32_t)(A_KV + s * A_BUF) * 2;

        // ---- scores S = Q K^T (split, fp32 accum); 16 rows x 64 keys ----
        float sacc[8][4];
        #pragma unroll
        for (int nf = 0; nf < 8; ++nf)
            #pragma unroll
            for (int x = 0; x < 4; ++x) sacc[nf][x] = 0.f;

        #pragma unroll
        for (int ks = 0; ks < 4; ++ks) {
            uint32_t ah[4], al[4];
            uint32_t qa = sb + (uint32_t)((warp * 16 + (lane & 15)) * ASTR) * 2
                        + (lane >> 4) * 16 + ks * 32;
            ldm_x4(ah, qa);
            ldm_x4(al, qa + A_QLO * 2);
            #pragma unroll
            for (int nb = 0; nb < 4; ++nb) {
                uint32_t bh4[4], bl4[4];
                uint32_t ka = kb + (uint32_t)((nb * 16 + (lane & 7) + ((lane >> 4) << 3)) * ASTR) * 2
                            + ((lane >> 3) & 1) * 16 + ks * 32;
                ldm_x4(bh4, ka);
                ldm_x4(bl4, ka + A_SUB * 2);
                #pragma unroll
                for (int hf = 0; hf < 2; ++hf) {
                    float* d = sacc[nb * 2 + hf];
                    mma16816(d, ah, bh4 + hf * 2);
                    mma16816(d, ah, bl4 + hf * 2);
                    mma16816(d, al, bh4 + hf * 2);
                }
            }
        }

        // ---- online softmax (registers + quad shuffles) ----
        {
            float r0 = -1e30f, r1 = -1e30f;
            #pragma unroll
            for (int nf = 0; nf < 8; ++nf) {
                r0 = fmaxf(r0, fmaxf(sacc[nf][0], sacc[nf][1]));
                r1 = fmaxf(r1, fmaxf(sacc[nf][2], sacc[nf][3]));
            }
            r0 = fmaxf(r0, __shfl_xor_sync(0xFFFFFFFFu, r0, 1));
            r0 = fmaxf(r0, __shfl_xor_sync(0xFFFFFFFFu, r0, 2));
            r1 = fmaxf(r1, __shfl_xor_sync(0xFFFFFFFFu, r1, 1));
            r1 = fmaxf(r1, __shfl_xor_sync(0xFFFFFFFFu, r1, 2));
            const float mn0 = fmaxf(m0, r0);
            const float mn1 = fmaxf(m1, r1);
            const float c0 = ex2a((m0 - mn0) * SC_L2E);
            const float c1 = ex2a((m1 - mn1) * SC_L2E);
            m0 = mn0; m1 = mn1;
            float rs0 = 0.f, rs1 = 0.f;
            #pragma unroll
            for (int nf = 0; nf < 8; ++nf) {
                float* sp = sacc[nf];
                sp[0] = ex2a((sp[0] - mn0) * SC_L2E);
                sp[1] = ex2a((sp[1] - mn0) * SC_L2E);
                sp[2] = ex2a((sp[2] - mn1) * SC_L2E);
                sp[3] = ex2a((sp[3] - mn1) * SC_L2E);
                rs0 += sp[0] + sp[1];
                rs1 += sp[2] + sp[3];
                o[nf][0] *= c0; o[nf][1] *= c0;
                o[nf][2] *= c1; o[nf][3] *= c1;
            }
            rs0 += __shfl_xor_sync(0xFFFFFFFFu, rs0, 1);
            rs0 += __shfl_xor_sync(0xFFFFFFFFu, rs0, 2);
            rs1 += __shfl_xor_sync(0xFFFFFFFFu, rs1, 1);
            rs1 += __shfl_xor_sync(0xFFFFFFFFu, rs1, 2);
            l0 = l0 * c0 + rs0;
            l1 = l1 * c1 + rs1;
        }

        // ---- O += P V (P split in-register, V split from smem) ----
        #pragma unroll
        for (int ks2 = 0; ks2 < 4; ++ks2) {
            uint32_t pah[4], pal[4];
            {
                float* s0 = sacc[2 * ks2];
                float* s1 = sacc[2 * ks2 + 1];
                pack_split(s0[0], s0[1], pah[0], pal[0]);
                pack_split(s0[2], s0[3], pah[1], pal[1]);
                pack_split(s1[0], s1[1], pah[2], pal[2]);
                pack_split(s1[2], s1[3], pah[3], pal[3]);
            }
            #pragma unroll
            for (int nblk = 0; nblk < 4; ++nblk) {
                uint32_t vh4[4], vl4[4];
                uint32_t va = kb + (uint32_t)(2 * A_SUB) * 2
                            + (uint32_t)((ks2 * 16 + (lane & 7) + ((lane >> 3) & 1) * 8) * ASTR
                                         + nblk * 16 + (lane >> 4) * 8) * 2;
                ldm_x4_t(vh4, va);
                ldm_x4_t(vl4, va + A_SUB * 2);
                #pragma unroll
                for (int hf = 0; hf < 2; ++hf) {
                    float* d = o[nblk * 2 + hf];
                    mma16816(d, pah, vh4 + hf * 2);
                    mma16816(d, pah, vl4 + hf * 2);
                    mma16816(d, pal, vh4 + hf * 2);
                }
            }
        }
        __syncthreads();
    }

    // ---- epilogue ----
    {
        const float i0 = 1.f / l0;
        const float i1 = 1.f / l1;
        const int row = b * SEQ + qt * 128 + warp * 16 + (lane >> 2);
        #pragma unroll
        for (int nf = 0; nf < 8; ++nf) {
            const int col = h * HD + nf * 8 + (lane & 3) * 2;
            *(float2*)(O + (size_t)row * HIDDEN + col) =
                make_float2(o[nf][0] * i0, o[nf][1] * i0);
            *(float2*)(O + (size_t)(row + 8) * HIDDEN + col) =
                make_float2(o[nf][2] * i1, o[nf][3] * i1);
        }
    }
}

// ---------------- launch ------------------------------------------------------
extern "C" void kernel_launch(void* const* d_in, const int* in_sizes, int n_in,
                              void* d_out, int out_size)
{
    const float* x  = (const float*)d_in[0];
    const float* wq = (const float*)d_in[1];
    const float* bq = (const float*)d_in[2];
    const float* wk = (const float*)d_in[3];
    const float* bk = (const float*)d_in[4];
    const float* wv = (const float*)d_in[5];
    const float* bv = (const float*)d_in[6];
    const float* wo = (const float*)d_in[7];
    const float* bo = (const float*)d_in[8];
    float* out = (float*)d_out;

    __nv_bfloat16 *qhi, *qlo, *khi, *klo, *vhi, *vlo;
    float* attn;
    cudaGetSymbolAddress((void**)&qhi, g_qhi);
    cudaGetSymbolAddress((void**)&qlo, g_qlo);
    cudaGetSymbolAddress((void**)&khi, g_khi);
    cudaGetSymbolAddress((void**)&klo, g_klo);
    cudaGetSymbolAddress((void**)&vhi, g_vhi);
    cudaGetSymbolAddress((void**)&vlo, g_vlo);
    cudaGetSymbolAddress((void**)&attn, g_attn);

    cudaFuncSetAttribute(mma_gemm_split,
                         cudaFuncAttributeMaxDynamicSharedMemorySize, GEMM_SMEM);
    cudaFuncSetAttribute(gqa_attn_tc,
                         cudaFuncAttributeMaxDynamicSharedMemorySize, A_SMEM);

    // Q/K/V projections -> pre-split bf16 hi/lo
    mma_gemm_split<<<dim3(HIDDEN / BN, MTOT / BM), 256, GEMM_SMEM>>>(
        x, wq, bq, nullptr, qhi, qlo, 1, MTOT, HIDDEN, HIDDEN);
    mma_gemm_split<<<dim3(KVDIM / BN, MTOT / BM), 256, GEMM_SMEM>>>(
        x, wk, bk, nullptr, khi, klo, 1, MTOT, KVDIM, HIDDEN);
    mma_gemm_split<<<dim3(KVDIM / BN, MTOT / BM), 256, GEMM_SMEM>>>(
        x, wv, bv, nullptr, vhi, vlo, 1, MTOT, KVDIM, HIDDEN);

    // tensor-core flash attention (8 warps/CTA)
    gqa_attn_tc<<<dim3(BATCH * NH, SEQ / 128), 256, A_SMEM>>>(
        qhi, qlo, khi, klo, vhi, vlo, attn);

    // output projection (fp32 out)
    mma_gemm_split<<<dim3(HIDDEN / BN, MTOT / BM), 256, GEMM_SMEM>>>(
        attn, wo, bo, out, nullptr, nullptr, 0, MTOT, HIDDEN, HIDDEN);
}

// round 15
// speedup vs baseline: 1.4445x; 1.3596x over previous
#include <cuda_runtime.h>
#include <cuda_fp16.h>
#include <cstdint>

// GroupQueryAttention: B=2, S=2048, HIDDEN=2048, H=32, HK=8, D=64
// R10: fp16 2-pass split everywhere (A_hi x (B_hi+B_lo)); err ~2^-12/stage.
// 1/3 fewer MMAs than bf16 3-pass at ~4e-4 predicted rel_err.

#define BATCH 2
#define SEQ 2048
#define HIDDEN 2048
#define NH 32
#define NKV 8
#define HD 64
#define KVDIM 512
#define MTOT (BATCH * SEQ)   // 4096

// ---------------- scratch (static device globals; no allocation) -------------
__device__ __half g_qh[MTOT * HIDDEN];
__device__ __half g_kh[MTOT * KVDIM], g_kl[MTOT * KVDIM];
__device__ __half g_vh[MTOT * KVDIM], g_vl[MTOT * KVDIM];
__device__ float g_attn[MTOT * HIDDEN];

// ======================= PTX helpers (arch-generic, sm_80+) ==================
__device__ __forceinline__ uint32_t smem_u32(const void* p) {
    uint32_t a;
    asm("{ .reg .u64 t; cvta.to.shared.u64 t, %1; cvt.u32.u64 %0, t; }"
        : "=r"(a) : "l"(p));
    return a;
}
__device__ __forceinline__ void ldm_x4(uint32_t* r, uint32_t addr) {
    asm volatile("ldmatrix.sync.aligned.m8n8.x4.shared.b16 {%0,%1,%2,%3}, [%4];"
                 : "=r"(r[0]), "=r"(r[1]), "=r"(r[2]), "=r"(r[3]) : "r"(addr));
}
__device__ __forceinline__ void ldm_x4_t(uint32_t* r, uint32_t addr) {
    asm volatile("ldmatrix.sync.aligned.m8n8.x4.trans.shared.b16 {%0,%1,%2,%3}, [%4];"
                 : "=r"(r[0]), "=r"(r[1]), "=r"(r[2]), "=r"(r[3]) : "r"(addr));
}
__device__ __forceinline__ void mma_h(float* d, const uint32_t* a, const uint32_t* b) {
    asm volatile("mma.sync.aligned.m16n8k16.row.col.f32.f16.f16.f32 "
                 "{%0,%1,%2,%3}, {%4,%5,%6,%7}, {%8,%9}, {%0,%1,%2,%3};"
                 : "+f"(d[0]), "+f"(d[1]), "+f"(d[2]), "+f"(d[3])
                 : "r"(a[0]), "r"(a[1]), "r"(a[2]), "r"(a[3]), "r"(b[0]), "r"(b[1]));
}
__device__ __forceinline__ float ex2a(float x) {
    float r;
    asm("ex2.approx.f32 %0, %1;" : "=f"(r) : "f"(x));
    return r;
}
#define CP_ASYNC16(dst, src) \
    asm volatile("cp.async.ca.shared.global [%0], [%1], 16;" :: "r"(dst), "l"(src))
#define CP_COMMIT() asm volatile("cp.async.commit_group;" ::: "memory")
#define CP_WAIT1() asm volatile("cp.async.wait_group 1;" ::: "memory")
#define CP_WAIT0() asm volatile("cp.async.wait_group 0;" ::: "memory")

// ---------------- fp16 store helpers -----------------------------------------
__device__ __forceinline__ void store_hi4(__half* hp, float4 v) {
    *(__half2*)(hp)     = __floats2half2_rn(v.x, v.y);
    *(__half2*)(hp + 2) = __floats2half2_rn(v.z, v.w);
}
__device__ __forceinline__ void store_split4(__half* hp, __half* lp, float4 v) {
    __half h0 = __float2half_rn(v.x), h1 = __float2half_rn(v.y);
    __half h2 = __float2half_rn(v.z), h3 = __float2half_rn(v.w);
    __half l0 = __float2half_rn(v.x - __half2float(h0));
    __half l1 = __float2half_rn(v.y - __half2float(h1));
    __half l2 = __float2half_rn(v.z - __half2float(h2));
    __half l3 = __float2half_rn(v.w - __half2float(h3));
    __half2 p;
    p.x = h0; p.y = h1; *(__half2*)(hp)     = p;
    p.x = h2; p.y = h3; *(__half2*)(hp + 2) = p;
    p.x = l0; p.y = l1; *(__half2*)(lp)     = p;
    p.x = l2; p.y = l3; *(__half2*)(lp + 2) = p;
}

// ============= fp16 2-pass tensor-core GEMM: C = A @ W^T + bias ==============
// A -> A_hi only; W -> W_hi + W_lo.  C = A_hi*W_hi + A_hi*W_lo.
// mode 0: fp32 C.  mode 1: fp16 hi+lo out.  mode 2: fp16 hi out only.
#define BM 128
#define BN 128
#define BK 32
#define STR 40
#define OFF_AHI 0
#define OFF_WHI (BM * STR)                 // 5120
#define OFF_WLO (BM * STR + BN * STR)      // 10240
#define STAGE_EL (BM * STR + 2 * BN * STR) // 15360
#define GEMM_SMEM (2 * STAGE_EL * 2)       // 61440 bytes

__global__ __launch_bounds__(256)
void mma_gemm_h(const float* __restrict__ A, const float* __restrict__ W,
                const float* __restrict__ bias, float* __restrict__ C,
                __half* __restrict__ Chi, __half* __restrict__ Clo,
                int mode, int M, int N, int K)
{
    extern __shared__ __align__(16) __half sm[];
    const int tid = threadIdx.x;
    const int lane = tid & 31, wid = tid >> 5;
    const int wm = wid & 3;
    const int wn = wid >> 2;
    const int bx = blockIdx.x, by = blockIdx.y;

    const float* Ab = A + (size_t)(by * BM) * K;
    const float* Wb = W + (size_t)(bx * BN) * K;

    float acc[2][8][4];
    #pragma unroll
    for (int i = 0; i < 2; ++i)
        #pragma unroll
        for (int j = 0; j < 8; ++j)
            #pragma unroll
            for (int t = 0; t < 4; ++t) acc[i][j][t] = 0.f;

    float4 ra[4], rb[4];
    const uint32_t sbase = smem_u32(sm);
    const uint32_t aoff = (uint32_t)((wm * 32 + (lane & 15)) * STR) * 2 + (lane >> 4) * 16;
    const uint32_t boff = (uint32_t)((wn * 64 + (lane & 7) + ((lane >> 4) << 3)) * STR) * 2
                        + ((lane >> 3) & 1) * 16;
    const int nit = K / BK;

    {
        #pragma unroll
        for (int l = 0; l < 4; ++l) {
            int slot = tid + l * 256;
            int r = slot >> 3, q = slot & 7;
            ra[l] = *(const float4*)(Ab + (size_t)r * K + q * 4);
            rb[l] = *(const float4*)(Wb + (size_t)r * K + q * 4);
        }
        #pragma unroll
        for (int l = 0; l < 4; ++l) {
            int slot = tid + l * 256;
            int r = slot >> 3, q = slot & 7;
            int off = r * STR + q * 4;
            store_hi4(sm + OFF_AHI + off, ra[l]);
            store_split4(sm + OFF_WHI + off, sm + OFF_WLO + off, rb[l]);
        }
        __syncthreads();
    }

    for (int i = 0; i < nit; ++i) {
        if (i + 1 < nit) {
            const int k0 = (i + 1) * BK;
            #pragma unroll
            for (int l = 0; l < 4; ++l) {
                int slot = tid + l * 256;
                int r = slot >> 3, q = slot & 7;
                ra[l] = *(const float4*)(Ab + (size_t)r * K + k0 + q * 4);
                rb[l] = *(const float4*)(Wb + (size_t)r * K + k0 + q * 4);
            }
        }
        {
            const uint32_t sa = sbase + (uint32_t)((i & 1) * STAGE_EL) * 2;
            #pragma unroll
            for (int ks = 0; ks < 2; ++ks) {
                const uint32_t kb = ks * 32;
                uint32_t ah[2][4], bh[4][4], bl[4][4];
                #pragma unroll
                for (int mf = 0; mf < 2; ++mf)
                    ldm_x4(ah[mf], sa + OFF_AHI * 2 + aoff + mf * (16 * STR * 2) + kb);
                #pragma unroll
                for (int nb = 0; nb < 4; ++nb) {
                    ldm_x4(bh[nb], sa + OFF_WHI * 2 + boff + nb * (16 * STR * 2) + kb);
                    ldm_x4(bl[nb], sa + OFF_WLO * 2 + boff + nb * (16 * STR * 2) + kb);
                }
                #pragma unroll
                for (int mf = 0; mf < 2; ++mf)
                    #pragma unroll
                    for (int nf = 0; nf < 8; ++nf) {
                        const uint32_t* bhp = &bh[nf >> 1][(nf & 1) * 2];
                        const uint32_t* blp = &bl[nf >> 1][(nf & 1) * 2];
                        mma_h(acc[mf][nf], ah[mf], bhp);
                        mma_h(acc[mf][nf], ah[mf], blp);
                    }
            }
        }
        if (i + 1 < nit) {
            __half* base = sm + ((i + 1) & 1) * STAGE_EL;
            #pragma unroll
            for (int l = 0; l < 4; ++l) {
                int slot = tid + l * 256;
                int r = slot >> 3, q = slot & 7;
                int off = r * STR + q * 4;
                store_hi4(base + OFF_AHI + off, ra[l]);
                store_split4(base + OFF_WHI + off, base + OFF_WLO + off, rb[l]);
            }
        }
        __syncthreads();
    }

    const int row0 = by * BM + wm * 32 + (lane >> 2);
    const int col0 = bx * BN + wn * 64 + 2 * (lane & 3);
    #pragma unroll
    for (int mf = 0; mf < 2; ++mf) {
        #pragma unroll
        for (int nf = 0; nf < 8; ++nf) {
            const int r0 = row0 + mf * 16;
            const int c = col0 + nf * 8;
            const float b0 = bias[c], b1 = bias[c + 1];
            float f00 = acc[mf][nf][0] + b0, f01 = acc[mf][nf][1] + b1;
            float f10 = acc[mf][nf][2] + b0, f11 = acc[mf][nf][3] + b1;
            if (mode == 0) {
                *(float2*)(C + (size_t)r0 * N + c) = make_float2(f00, f01);
                *(float2*)(C + (size_t)(r0 + 8) * N + c) = make_float2(f10, f11);
            } else if (mode == 2) {
                *(__half2*)(Chi + (size_t)r0 * N + c) = __floats2half2_rn(f00, f01);
                *(__half2*)(Chi + (size_t)(r0 + 8) * N + c) = __floats2half2_rn(f10, f11);
            } else {
                __half h0 = __float2half_rn(f00), h1 = __float2half_rn(f01);
                __half2 hh; hh.x = h0; hh.y = h1;
                __half2 ll;
                ll.x = __float2half_rn(f00 - __half2float(h0));
                ll.y = __float2half_rn(f01 - __half2float(h1));
                *(__half2*)(Chi + (size_t)r0 * N + c) = hh;
                *(__half2*)(Clo + (size_t)r0 * N + c) = ll;
                h0 = __float2half_rn(f10); h1 = __float2half_rn(f11);
                hh.x = h0; hh.y = h1;
                ll.x = __float2half_rn(f10 - __half2float(h0));
                ll.y = __float2half_rn(f11 - __half2float(h1));
                *(__half2*)(Chi + (size_t)(r0 + 8) * N + c) = hh;
                *(__half2*)(Clo + (size_t)(r0 + 8) * N + c) = ll;
            }
        }
    }
}

// =================== fp16 tensor-core flash attention =========================
// 256 threads (8 warps), 128 q rows -> 16 per warp; 64-key tiles, 2-stage async.
// S = q_hi * (k_hi + k_lo);  O += P_fp16 * (v_hi + v_lo).
#define ASTR 72
#define A_KV  (128 * ASTR)          // Q_hi region: 9216 elems
#define A_SUB (64 * ASTR)           // 4608
#define A_BUF (4 * A_SUB)           // 18432 per stage (k_h,k_l,v_h,v_l)
#define A_SMEM ((A_KV + 2 * A_BUF) * 2)   // 92160 bytes
#define SC_L2E 0.18033688011112042f       // (1/sqrt(64)) * log2(e)

__global__ __launch_bounds__(256)
void gqa_attn_h(const __half* __restrict__ qh_g,
                const __half* __restrict__ kh_g, const __half* __restrict__ kl_g,
                const __half* __restrict__ vh_g, const __half* __restrict__ vl_g,
                float* __restrict__ O)
{
    extern __shared__ __align__(16) __half smb[];
    const int tid = threadIdx.x;
    const int lane = tid & 31, warp = tid >> 5;
    const int bh = blockIdx.x, qt = blockIdx.y;
    const int b = bh / NH, h = bh % NH;
    const int kvh = h >> 2;

    const uint32_t sb = smem_u32(smb);
    const __half* qh = qh_g + (size_t)(b * SEQ + qt * 128) * HIDDEN + h * HD;
    const __half* kh = kh_g + (size_t)(b * SEQ) * KVDIM + kvh * HD;
    const __half* kl = kl_g + (size_t)(b * SEQ) * KVDIM + kvh * HD;
    const __half* vh = vh_g + (size_t)(b * SEQ) * KVDIM + kvh * HD;
    const __half* vl = vl_g + (size_t)(b * SEQ) * KVDIM + kvh * HD;

    // ---- load Q_hi tile: 1024 16B slots over 256 threads ----
    #pragma unroll
    for (int l = 0; l < 4; ++l) {
        int idx = tid + l * 256;
        int r = idx >> 3, c = idx & 7;
        *(uint4*)(smb + r * ASTR + c * 8) = *(const uint4*)(qh + (size_t)r * HIDDEN + c * 8);
    }

    auto stage = [&](int t, int s) {
        #pragma unroll
        for (int l = 0; l < 8; ++l) {
            int idx = tid + l * 256;
            int sel = idx >> 9, rem = idx & 511, r = rem >> 3, c = rem & 7;
            const __half* src =
                (sel == 0 ? kh : sel == 1 ? kl : sel == 2 ? vh : vl)
                + (size_t)(t * 64 + r) * KVDIM + c * 8;
            uint32_t dst = sb + (uint32_t)(A_KV + s * A_BUF + sel * A_SUB + r * ASTR + c * 8) * 2;
            CP_ASYNC16(dst, src);
        }
    };

    float m0 = -1e30f, m1 = -1e30f, l0 = 0.f, l1 = 0.f;
    float o[8][4];
    #pragma unroll
    for (int nf = 0; nf < 8; ++nf)
        #pragma unroll
        for (int t = 0; t < 4; ++t) o[nf][t] = 0.f;

    stage(0, 0);
    CP_COMMIT();

    for (int t = 0; t < SEQ / 64; ++t) {
        const int s = t & 1;
        if (t + 1 < SEQ / 64) { stage(t + 1, s ^ 1); CP_COMMIT(); CP_WAIT1(); }
        else CP_WAIT0();
        __syncthreads();

        const uint32_t kb = sb + (uint32_t)(A_KV + s * A_BUF) * 2;

        // ---- scores S = q_hi (k_hi + k_lo); 16 rows x 64 keys ----
        float sacc[8][4];
        #pragma unroll
        for (int nf = 0; nf < 8; ++nf)
            #pragma unroll
            for (int x = 0; x < 4; ++x) sacc[nf][x] = 0.f;

        #pragma unroll
        for (int ks = 0; ks < 4; ++ks) {
            uint32_t ah[4];
            uint32_t qa = sb + (uint32_t)((warp * 16 + (lane & 15)) * ASTR) * 2
                        + (lane >> 4) * 16 + ks * 32;
            ldm_x4(ah, qa);
            #pragma unroll
            for (int nb = 0; nb < 4; ++nb) {
                uint32_t bh4[4], bl4[4];
                uint32_t ka = kb + (uint32_t)((nb * 16 + (lane & 7) + ((lane >> 4) << 3)) * ASTR) * 2
                            + ((lane >> 3) & 1) * 16 + ks * 32;
                ldm_x4(bh4, ka);
                ldm_x4(bl4, ka + A_SUB * 2);
                #pragma unroll
                for (int hf = 0; hf < 2; ++hf) {
                    float* d = sacc[nb * 2 + hf];
                    mma_h(d, ah, bh4 + hf * 2);
                    mma_h(d, ah, bl4 + hf * 2);
                }
            }
        }

        // ---- online softmax (registers + quad shuffles) ----
        {
            float r0 = -1e30f, r1 = -1e30f;
            #pragma unroll
            for (int nf = 0; nf < 8; ++nf) {
                r0 = fmaxf(r0, fmaxf(sacc[nf][0], sacc[nf][1]));
                r1 = fmaxf(r1, fmaxf(sacc[nf][2], sacc[nf][3]));
            }
            r0 = fmaxf(r0, __shfl_xor_sync(0xFFFFFFFFu, r0, 1));
            r0 = fmaxf(r0, __shfl_xor_sync(0xFFFFFFFFu, r0, 2));
            r1 = fmaxf(r1, __shfl_xor_sync(0xFFFFFFFFu, r1, 1));
            r1 = fmaxf(r1, __shfl_xor_sync(0xFFFFFFFFu, r1, 2));
            const float mn0 = fmaxf(m0, r0);
            const float mn1 = fmaxf(m1, r1);
            const float c0 = ex2a((m0 - mn0) * SC_L2E);
            const float c1 = ex2a((m1 - mn1) * SC_L2E);
            m0 = mn0; m1 = mn1;
            float rs0 = 0.f, rs1 = 0.f;
            #pragma unroll
            for (int nf = 0; nf < 8; ++nf) {
                float* sp = sacc[nf];
                sp[0] = ex2a((sp[0] - mn0) * SC_L2E);
                sp[1] = ex2a((sp[1] - mn0) * SC_L2E);
                sp[2] = ex2a((sp[2] - mn1) * SC_L2E);
                sp[3] = ex2a((sp[3] - mn1) * SC_L2E);
                rs0 += sp[0] + sp[1];
                rs1 += sp[2] + sp[3];
                o[nf][0] *= c0; o[nf][1] *= c0;
                o[nf][2] *= c1; o[nf][3] *= c1;
            }
            rs0 += __shfl_xor_sync(0xFFFFFFFFu, rs0, 1);
            rs0 += __shfl_xor_sync(0xFFFFFFFFu, rs0, 2);
            rs1 += __shfl_xor_sync(0xFFFFFFFFu, rs1, 1);
            rs1 += __shfl_xor_sync(0xFFFFFFFFu, rs1, 2);
            l0 = l0 * c0 + rs0;
            l1 = l1 * c1 + rs1;
        }

        // ---- O += P_fp16 (v_hi + v_lo) ----
        #pragma unroll
        for (int ks2 = 0; ks2 < 4; ++ks2) {
            uint32_t ph[4];
            {
                float* s0 = sacc[2 * ks2];
                float* s1 = sacc[2 * ks2 + 1];
                __half2 t0 = __floats2half2_rn(s0[0], s0[1]);
                __half2 t1 = __floats2half2_rn(s0[2], s0[3]);
                __half2 t2 = __floats2half2_rn(s1[0], s1[1]);
                __half2 t3 = __floats2half2_rn(s1[2], s1[3]);
                ph[0] = *(uint32_t*)&t0;
                ph[1] = *(uint32_t*)&t1;
                ph[2] = *(uint32_t*)&t2;
                ph[3] = *(uint32_t*)&t3;
            }
            #pragma unroll
            for (int nblk = 0; nblk < 4; ++nblk) {
                uint32_t vh4[4], vl4[4];
                uint32_t va = kb + (uint32_t)(2 * A_SUB) * 2
                            + (uint32_t)((ks2 * 16 + (lane & 7) + ((lane >> 3) & 1) * 8) * ASTR
                                         + nblk * 16 + (lane >> 4) * 8) * 2;
                ldm_x4_t(vh4, va);
                ldm_x4_t(vl4, va + A_SUB * 2);
                #pragma unroll
                for (int hf = 0; hf < 2; ++hf) {
                    float* d = o[nblk * 2 + hf];
                    mma_h(d, ph, vh4 + hf * 2);
                    mma_h(d, ph, vl4 + hf * 2);
                }
            }
        }
        __syncthreads();
    }

    // ---- epilogue (fp32 attn out) ----
    {
        const float i0 = 1.f / l0;
        const float i1 = 1.f / l1;
        const int row = b * SEQ + qt * 128 + warp * 16 + (lane >> 2);
        #pragma unroll
        for (int nf = 0; nf < 8; ++nf) {
            const int col = h * HD + nf * 8 + (lane & 3) * 2;
            *(float2*)(O + (size_t)row * HIDDEN + col) =
                make_float2(o[nf][0] * i0, o[nf][1] * i0);
            *(float2*)(O + (size_t)(row + 8) * HIDDEN + col) =
                make_float2(o[nf][2] * i1, o[nf][3] * i1);
        }
    }
}

// ---------------- launch ------------------------------------------------------
extern "C" void kernel_launch(void* const* d_in, const int* in_sizes, int n_in,
                              void* d_out, int out_size)
{
    const float* x  = (const float*)d_in[0];
    const float* wq = (const float*)d_in[1];
    const float* bq = (const float*)d_in[2];
    const float* wk = (const float*)d_in[3];
    const float* bk = (const float*)d_in[4];
    const float* wv = (const float*)d_in[5];
    const float* bv = (const float*)d_in[6];
    const float* wo = (const float*)d_in[7];
    const float* bo = (const float*)d_in[8];
    float* out = (float*)d_out;

    __half *qh, *kh, *kl, *vh, *vl;
    float* attn;
    cudaGetSymbolAddress((void**)&qh, g_qh);
    cudaGetSymbolAddress((void**)&kh, g_kh);
    cudaGetSymbolAddress((void**)&kl, g_kl);
    cudaGetSymbolAddress((void**)&vh, g_vh);
    cudaGetSymbolAddress((void**)&vl, g_vl);
    cudaGetSymbolAddress((void**)&attn, g_attn);

    cudaFuncSetAttribute(mma_gemm_h,
                         cudaFuncAttributeMaxDynamicSharedMemorySize, GEMM_SMEM);
    cudaFuncSetAttribute(gqa_attn_h,
                         cudaFuncAttributeMaxDynamicSharedMemorySize, A_SMEM);

    // projections: Q -> hi only; K,V -> hi+lo
    mma_gemm_h<<<dim3(HIDDEN / BN, MTOT / BM), 256, GEMM_SMEM>>>(
        x, wq, bq, nullptr, qh, nullptr, 2, MTOT, HIDDEN, HIDDEN);
    mma_gemm_h<<<dim3(KVDIM / BN, MTOT / BM), 256, GEMM_SMEM>>>(
        x, wk, bk, nullptr, kh, kl, 1, MTOT, KVDIM, HIDDEN);
    mma_gemm_h<<<dim3(KVDIM / BN, MTOT / BM), 256, GEMM_SMEM>>>(
        x, wv, bv, nullptr, vh, vl, 1, MTOT, KVDIM, HIDDEN);

    // fp16 tensor-core flash attention
    gqa_attn_h<<<dim3(BATCH * NH, SEQ / 128), 256, A_SMEM>>>(
        qh, kh, kl, vh, vl, attn);

    // output projection (fp32 out)
    mma_gemm_h<<<dim3(HIDDEN / BN, MTOT / BM), 256, GEMM_SMEM>>>(
        attn, wo, bo, out, nullptr, nullptr, 0, MTOT, HIDDEN, HIDDEN);
}

// round 17
// speedup vs baseline: 1.8711x; 1.2953x over previous
#include <cuda_runtime.h>
#include <cuda_fp16.h>
#include <cstdint>

// GroupQueryAttention: B=2, S=2048, HIDDEN=2048, H=32, HK=8, D=64
// R15: pure single-pass fp16 (fp32 accum) everywhere. Halves MMA volume and
// attention smem traffic vs R10's 2-pass. Predicted rel_err ~3-5e-4.

#define BATCH 2
#define SEQ 2048
#define HIDDEN 2048
#define NH 32
#define NKV 8
#define HD 64
#define KVDIM 512
#define MTOT (BATCH * SEQ)   // 4096

// ---------------- scratch (static device globals; no allocation) -------------
__device__ __half g_qh[MTOT * HIDDEN];
__device__ __half g_kh[MTOT * KVDIM];
__device__ __half g_vh[MTOT * KVDIM];
__device__ float g_attn[MTOT * HIDDEN];

// ======================= PTX helpers (arch-generic, sm_80+) ==================
__device__ __forceinline__ uint32_t smem_u32(const void* p) {
    uint32_t a;
    asm("{ .reg .u64 t; cvta.to.shared.u64 t, %1; cvt.u32.u64 %0, t; }"
        : "=r"(a) : "l"(p));
    return a;
}
__device__ __forceinline__ void ldm_x4(uint32_t* r, uint32_t addr) {
    asm volatile("ldmatrix.sync.aligned.m8n8.x4.shared.b16 {%0,%1,%2,%3}, [%4];"
                 : "=r"(r[0]), "=r"(r[1]), "=r"(r[2]), "=r"(r[3]) : "r"(addr));
}
__device__ __forceinline__ void ldm_x4_t(uint32_t* r, uint32_t addr) {
    asm volatile("ldmatrix.sync.aligned.m8n8.x4.trans.shared.b16 {%0,%1,%2,%3}, [%4];"
                 : "=r"(r[0]), "=r"(r[1]), "=r"(r[2]), "=r"(r[3]) : "r"(addr));
}
__device__ __forceinline__ void mma_h(float* d, const uint32_t* a, const uint32_t* b) {
    asm volatile("mma.sync.aligned.m16n8k16.row.col.f32.f16.f16.f32 "
                 "{%0,%1,%2,%3}, {%4,%5,%6,%7}, {%8,%9}, {%0,%1,%2,%3};"
                 : "+f"(d[0]), "+f"(d[1]), "+f"(d[2]), "+f"(d[3])
                 : "r"(a[0]), "r"(a[1]), "r"(a[2]), "r"(a[3]), "r"(b[0]), "r"(b[1]));
}
__device__ __forceinline__ float ex2a(float x) {
    float r;
    asm("ex2.approx.f32 %0, %1;" : "=f"(r) : "f"(x));
    return r;
}
#define CP_ASYNC16(dst, src) \
    asm volatile("cp.async.ca.shared.global [%0], [%1], 16;" :: "r"(dst), "l"(src))
#define CP_COMMIT() asm volatile("cp.async.commit_group;" ::: "memory")
#define CP_WAIT1() asm volatile("cp.async.wait_group 1;" ::: "memory")
#define CP_WAIT0() asm volatile("cp.async.wait_group 0;" ::: "memory")

__device__ __forceinline__ void store_hi4(__half* hp, float4 v) {
    *(__half2*)(hp)     = __floats2half2_rn(v.x, v.y);
    *(__half2*)(hp + 2) = __floats2half2_rn(v.z, v.w);
}

// ============= single-pass fp16 tensor-core GEMM: C = A @ W^T + bias =========
// mode 0: fp32 C.  mode 2: fp16 C.
#define BM 128
#define BN 128
#define BK 32
#define STR 40
#define OFF_AHI 0
#define OFF_WHI (BM * STR)            // 5120
#define STAGE_EL (BM * STR + BN * STR) // 10240
#define GEMM_SMEM (2 * STAGE_EL * 2)   // 40960 bytes

__global__ __launch_bounds__(256)
void mma_gemm_h(const float* __restrict__ A, const float* __restrict__ W,
                const float* __restrict__ bias, float* __restrict__ C,
                __half* __restrict__ Chi, int mode, int M, int N, int K)
{
    extern __shared__ __align__(16) __half sm[];
    const int tid = threadIdx.x;
    const int lane = tid & 31, wid = tid >> 5;
    const int wm = wid & 3;
    const int wn = wid >> 2;
    const int bx = blockIdx.x, by = blockIdx.y;

    const float* Ab = A + (size_t)(by * BM) * K;
    const float* Wb = W + (size_t)(bx * BN) * K;

    float acc[2][8][4];
    #pragma unroll
    for (int i = 0; i < 2; ++i)
        #pragma unroll
        for (int j = 0; j < 8; ++j)
            #pragma unroll
            for (int t = 0; t < 4; ++t) acc[i][j][t] = 0.f;

    float4 ra[4], rb[4];
    const uint32_t sbase = smem_u32(sm);
    const uint32_t aoff = (uint32_t)((wm * 32 + (lane & 15)) * STR) * 2 + (lane >> 4) * 16;
    const uint32_t boff = (uint32_t)((wn * 64 + (lane & 7) + ((lane >> 4) << 3)) * STR) * 2
                        + ((lane >> 3) & 1) * 16;
    const int nit = K / BK;

    {
        #pragma unroll
        for (int l = 0; l < 4; ++l) {
            int slot = tid + l * 256;
            int r = slot >> 3, q = slot & 7;
            ra[l] = *(const float4*)(Ab + (size_t)r * K + q * 4);
            rb[l] = *(const float4*)(Wb + (size_t)r * K + q * 4);
        }
        #pragma unroll
        for (int l = 0; l < 4; ++l) {
            int slot = tid + l * 256;
            int r = slot >> 3, q = slot & 7;
            int off = r * STR + q * 4;
            store_hi4(sm + OFF_AHI + off, ra[l]);
            store_hi4(sm + OFF_WHI + off, rb[l]);
        }
        __syncthreads();
    }

    for (int i = 0; i < nit; ++i) {
        if (i + 1 < nit) {
            const int k0 = (i + 1) * BK;
            #pragma unroll
            for (int l = 0; l < 4; ++l) {
                int slot = tid + l * 256;
                int r = slot >> 3, q = slot & 7;
                ra[l] = *(const float4*)(Ab + (size_t)r * K + k0 + q * 4);
                rb[l] = *(const float4*)(Wb + (size_t)r * K + k0 + q * 4);
            }
        }
        {
            const uint32_t sa = sbase + (uint32_t)((i & 1) * STAGE_EL) * 2;
            #pragma unroll
            for (int ks = 0; ks < 2; ++ks) {
                const uint32_t kb = ks * 32;
                uint32_t ah[2][4], bh[4][4];
                #pragma unroll
                for (int mf = 0; mf < 2; ++mf)
                    ldm_x4(ah[mf], sa + OFF_AHI * 2 + aoff + mf * (16 * STR * 2) + kb);
                #pragma unroll
                for (int nb = 0; nb < 4; ++nb)
                    ldm_x4(bh[nb], sa + OFF_WHI * 2 + boff + nb * (16 * STR * 2) + kb);
                #pragma unroll
                for (int mf = 0; mf < 2; ++mf)
                    #pragma unroll
                    for (int nf = 0; nf < 8; ++nf)
                        mma_h(acc[mf][nf], ah[mf], &bh[nf >> 1][(nf & 1) * 2]);
            }
        }
        if (i + 1 < nit) {
            __half* base = sm + ((i + 1) & 1) * STAGE_EL;
            #pragma unroll
            for (int l = 0; l < 4; ++l) {
                int slot = tid + l * 256;
                int r = slot >> 3, q = slot & 7;
                int off = r * STR + q * 4;
                store_hi4(base + OFF_AHI + off, ra[l]);
                store_hi4(base + OFF_WHI + off, rb[l]);
            }
        }
        __syncthreads();
    }

    const int row0 = by * BM + wm * 32 + (lane >> 2);
    const int col0 = bx * BN + wn * 64 + 2 * (lane & 3);
    #pragma unroll
    for (int mf = 0; mf < 2; ++mf) {
        #pragma unroll
        for (int nf = 0; nf < 8; ++nf) {
            const int r0 = row0 + mf * 16;
            const int c = col0 + nf * 8;
            const float b0 = bias[c], b1 = bias[c + 1];
            float f00 = acc[mf][nf][0] + b0, f01 = acc[mf][nf][1] + b1;
            float f10 = acc[mf][nf][2] + b0, f11 = acc[mf][nf][3] + b1;
            if (mode == 0) {
                *(float2*)(C + (size_t)r0 * N + c) = make_float2(f00, f01);
                *(float2*)(C + (size_t)(r0 + 8) * N + c) = make_float2(f10, f11);
            } else {
                *(__half2*)(Chi + (size_t)r0 * N + c) = __floats2half2_rn(f00, f01);
                *(__half2*)(Chi + (size_t)(r0 + 8) * N + c) = __floats2half2_rn(f10, f11);
            }
        }
    }
}

// =================== single-pass fp16 flash attention =========================
// 256 threads (8 warps), 128 q rows -> 16 per warp; 64-key tiles, 2-stage async.
#define ASTR 72
#define A_KV  (128 * ASTR)          // Q region: 9216 elems
#define A_SUB (64 * ASTR)           // 4608
#define A_BUF (2 * A_SUB)           // 9216 per stage (k, v)
#define A_SMEM ((A_KV + 2 * A_BUF) * 2)   // 55296 bytes
#define SC_L2E 0.18033688011112042f       // (1/sqrt(64)) * log2(e)

__global__ __launch_bounds__(256)
void gqa_attn_h(const __half* __restrict__ qh_g,
                const __half* __restrict__ kh_g, const __half* __restrict__ vh_g,
                float* __restrict__ O)
{
    extern __shared__ __align__(16) __half smb[];
    const int tid = threadIdx.x;
    const int lane = tid & 31, warp = tid >> 5;
    const int bh = blockIdx.x, qt = blockIdx.y;
    const int b = bh / NH, h = bh % NH;
    const int kvh = h >> 2;

    const uint32_t sb = smem_u32(smb);
    const __half* qh = qh_g + (size_t)(b * SEQ + qt * 128) * HIDDEN + h * HD;
    const __half* kh = kh_g + (size_t)(b * SEQ) * KVDIM + kvh * HD;
    const __half* vh = vh_g + (size_t)(b * SEQ) * KVDIM + kvh * HD;

    // ---- load Q tile: 1024 16B slots over 256 threads ----
    #pragma unroll
    for (int l = 0; l < 4; ++l) {
        int idx = tid + l * 256;
        int r = idx >> 3, c = idx & 7;
        *(uint4*)(smb + r * ASTR + c * 8) = *(const uint4*)(qh + (size_t)r * HIDDEN + c * 8);
    }

    auto stage = [&](int t, int s) {
        #pragma unroll
        for (int l = 0; l < 4; ++l) {
            int idx = tid + l * 256;
            int sel = idx >> 9, rem = idx & 511, r = rem >> 3, c = rem & 7;
            const __half* src = (sel ? vh : kh) + (size_t)(t * 64 + r) * KVDIM + c * 8;
            uint32_t dst = sb + (uint32_t)(A_KV + s * A_BUF + sel * A_SUB + r * ASTR + c * 8) * 2;
            CP_ASYNC16(dst, src);
        }
    };

    float m0 = -1e30f, m1 = -1e30f, l0 = 0.f, l1 = 0.f;
    float o[8][4];
    #pragma unroll
    for (int nf = 0; nf < 8; ++nf)
        #pragma unroll
        for (int t = 0; t < 4; ++t) o[nf][t] = 0.f;

    stage(0, 0);
    CP_COMMIT();

    for (int t = 0; t < SEQ / 64; ++t) {
        const int s = t & 1;
        if (t + 1 < SEQ / 64) { stage(t + 1, s ^ 1); CP_COMMIT(); CP_WAIT1(); }
        else CP_WAIT0();
        __syncthreads();

        const uint32_t kb = sb + (uint32_t)(A_KV + s * A_BUF) * 2;

        // ---- scores S = q k^T; 16 rows x 64 keys ----
        float sacc[8][4];
        #pragma unroll
        for (int nf = 0; nf < 8; ++nf)
            #pragma unroll
            for (int x = 0; x < 4; ++x) sacc[nf][x] = 0.f;

        #pragma unroll
        for (int ks = 0; ks < 4; ++ks) {
            uint32_t ah[4];
            uint32_t qa = sb + (uint32_t)((warp * 16 + (lane & 15)) * ASTR) * 2
                        + (lane >> 4) * 16 + ks * 32;
            ldm_x4(ah, qa);
            #pragma unroll
            for (int nb = 0; nb < 4; ++nb) {
                uint32_t bh4[4];
                uint32_t ka = kb + (uint32_t)((nb * 16 + (lane & 7) + ((lane >> 4) << 3)) * ASTR) * 2
                            + ((lane >> 3) & 1) * 16 + ks * 32;
                ldm_x4(bh4, ka);
                #pragma unroll
                for (int hf = 0; hf < 2; ++hf)
                    mma_h(sacc[nb * 2 + hf], ah, bh4 + hf * 2);
            }
        }

        // ---- online softmax (registers + quad shuffles) ----
        {
            float r0 = -1e30f, r1 = -1e30f;
            #pragma unroll
            for (int nf = 0; nf < 8; ++nf) {
                r0 = fmaxf(r0, fmaxf(sacc[nf][0], sacc[nf][1]));
                r1 = fmaxf(r1, fmaxf(sacc[nf][2], sacc[nf][3]));
            }
            r0 = fmaxf(r0, __shfl_xor_sync(0xFFFFFFFFu, r0, 1));
            r0 = fmaxf(r0, __shfl_xor_sync(0xFFFFFFFFu, r0, 2));
            r1 = fmaxf(r1, __shfl_xor_sync(0xFFFFFFFFu, r1, 1));
            r1 = fmaxf(r1, __shfl_xor_sync(0xFFFFFFFFu, r1, 2));
            const float mn0 = fmaxf(m0, r0);
            const float mn1 = fmaxf(m1, r1);
            const float c0 = ex2a((m0 - mn0) * SC_L2E);
            const float c1 = ex2a((m1 - mn1) * SC_L2E);
            m0 = mn0; m1 = mn1;
            float rs0 = 0.f, rs1 = 0.f;
            #pragma unroll
            for (int nf = 0; nf < 8; ++nf) {
                float* sp = sacc[nf];
                sp[0] = ex2a((sp[0] - mn0) * SC_L2E);
                sp[1] = ex2a((sp[1] - mn0) * SC_L2E);
                sp[2] = ex2a((sp[2] - mn1) * SC_L2E);
                sp[3] = ex2a((sp[3] - mn1) * SC_L2E);
                rs0 += sp[0] + sp[1];
                rs1 += sp[2] + sp[3];
                o[nf][0] *= c0; o[nf][1] *= c0;
                o[nf][2] *= c1; o[nf][3] *= c1;
            }
            rs0 += __shfl_xor_sync(0xFFFFFFFFu, rs0, 1);
            rs0 += __shfl_xor_sync(0xFFFFFFFFu, rs0, 2);
            rs1 += __shfl_xor_sync(0xFFFFFFFFu, rs1, 1);
            rs1 += __shfl_xor_sync(0xFFFFFFFFu, rs1, 2);
            l0 = l0 * c0 + rs0;
            l1 = l1 * c1 + rs1;
        }

        // ---- O += P v ----
        #pragma unroll
        for (int ks2 = 0; ks2 < 4; ++ks2) {
            uint32_t ph[4];
            {
                float* s0 = sacc[2 * ks2];
                float* s1 = sacc[2 * ks2 + 1];
                __half2 t0 = __floats2half2_rn(s0[0], s0[1]);
                __half2 t1 = __floats2half2_rn(s0[2], s0[3]);
                __half2 t2 = __floats2half2_rn(s1[0], s1[1]);
                __half2 t3 = __floats2half2_rn(s1[2], s1[3]);
                ph[0] = *(uint32_t*)&t0;
                ph[1] = *(uint32_t*)&t1;
                ph[2] = *(uint32_t*)&t2;
                ph[3] = *(uint32_t*)&t3;
            }
            #pragma unroll
            for (int nblk = 0; nblk < 4; ++nblk) {
                uint32_t vh4[4];
                uint32_t va = kb + (uint32_t)(A_SUB) * 2
                            + (uint32_t)((ks2 * 16 + (lane & 7) + ((lane >> 3) & 1) * 8) * ASTR
                                         + nblk * 16 + (lane >> 4) * 8) * 2;
                ldm_x4_t(vh4, va);
                #pragma unroll
                for (int hf = 0; hf < 2; ++hf)
                    mma_h(o[nblk * 2 + hf], ph, vh4 + hf * 2);
            }
        }
        __syncthreads();
    }

    // ---- epilogue (fp32 attn out) ----
    {
        const float i0 = 1.f / l0;
        const float i1 = 1.f / l1;
        const int row = b * SEQ + qt * 128 + warp * 16 + (lane >> 2);
        #pragma unroll
        for (int nf = 0; nf < 8; ++nf) {
            const int col = h * HD + nf * 8 + (lane & 3) * 2;
            *(float2*)(O + (size_t)row * HIDDEN + col) =
                make_float2(o[nf][0] * i0, o[nf][1] * i0);
            *(float2*)(O + (size_t)(row + 8) * HIDDEN + col) =
                make_float2(o[nf][2] * i1, o[nf][3] * i1);
        }
    }
}

// ---------------- launch ------------------------------------------------------
extern "C" void kernel_launch(void* const* d_in, const int* in_sizes, int n_in,
                              void* d_out, int out_size)
{
    const float* x  = (const float*)d_in[0];
    const float* wq = (const float*)d_in[1];
    const float* bq = (const float*)d_in[2];
    const float* wk = (const float*)d_in[3];
    const float* bk = (const float*)d_in[4];
    const float* wv = (const float*)d_in[5];
    const float* bv = (const float*)d_in[6];
    const float* wo = (const float*)d_in[7];
    const float* bo = (const float*)d_in[8];
    float* out = (float*)d_out;

    __half *qh, *kh, *vh;
    float* attn;
    cudaGetSymbolAddress((void**)&qh, g_qh);
    cudaGetSymbolAddress((void**)&kh, g_kh);
    cudaGetSymbolAddress((void**)&vh, g_vh);
    cudaGetSymbolAddress((void**)&attn, g_attn);

    cudaFuncSetAttribute(mma_gemm_h,
                         cudaFuncAttributeMaxDynamicSharedMemorySize, GEMM_SMEM);
    cudaFuncSetAttribute(gqa_attn_h,
                         cudaFuncAttributeMaxDynamicSharedMemorySize, A_SMEM);

    // projections (single-pass fp16, fp16 out)
    mma_gemm_h<<<dim3(HIDDEN / BN, MTOT / BM), 256, GEMM_SMEM>>>(
        x, wq, bq, nullptr, qh, 2, MTOT, HIDDEN, HIDDEN);
    mma_gemm_h<<<dim3(KVDIM / BN, MTOT / BM), 256, GEMM_SMEM>>>(
        x, wk, bk, nullptr, kh, 2, MTOT, KVDIM, HIDDEN);
    mma_gemm_h<<<dim3(KVDIM / BN, MTOT / BM), 256, GEMM_SMEM>>>(
        x, wv, bv, nullptr, vh, 2, MTOT, KVDIM, HIDDEN);

    // single-pass fp16 flash attention
    gqa_attn_h<<<dim3(BATCH * NH, SEQ / 128), 256, A_SMEM>>>(
        qh, kh, vh, attn);

    // output projection (fp32 out)
    mma_gemm_h<<<dim3(HIDDEN / BN, MTOT / BM), 256, GEMM_SMEM>>>(
        attn, wo, bo, out, nullptr, 0, MTOT, HIDDEN, HIDDEN);
}